// round 9
// baseline (speedup 1.0000x reference)
#include <cuda_runtime.h>

// SmartDoorClassifierv1 — fused CNN (LIF collapses: alpha = exp(-200) == 0 in fp32).
// Round 8: kill residual spill at 3 CTAs/SM. Stage 2 split over output rows
// (e-halves): acc 32 -> 16 regs, patch 24 -> 18 regs, running max across passes.

#define THREADS 256

// dynamic smem layout (float indices)
//  p1p : 8 x 34 x 34 = 9248   (stage-1 pooled, 1-halo, zeroed)
//  p2p : 8 x 18 x 18 = 2592   (stage-2 pooled, 1-halo, zeroed)
//  p3  : 512                  (flatten order)
//  sw1 : 64, sw2: 576, sw3: 576, red: 16
#define OFF_P1   0
#define OFF_P2   9248
#define OFF_P3   11840
#define OFF_W1   12352
#define OFF_W2   (OFF_W1 + 64)
#define OFF_W3   (OFF_W2 + 576)
#define OFF_RED  (OFF_W3 + 576)
#define SMEM_FLOATS (OFF_RED + 16)

__global__ __launch_bounds__(THREADS, 3)
void snn_fused_kernel(const float* __restrict__ x,
                      const float* __restrict__ w1,
                      const float* __restrict__ w2,
                      const float* __restrict__ w3,
                      const float* __restrict__ wfc,
                      float* __restrict__ out)
{
    extern __shared__ float smem[];
    float* p1p = smem + OFF_P1;
    float* p2p = smem + OFF_P2;
    float* p3  = smem + OFF_P3;
    float* sw1 = smem + OFF_W1;
    float* sw2 = smem + OFF_W2;
    float* sw3 = smem + OFF_W3;
    float* red = smem + OFF_RED;

    const int tid = threadIdx.x;
    const int n   = blockIdx.x;

    // ---- init: weights + zero-filled padded planes ----
    if (tid < 64) sw1[tid] = w1[tid];
    for (int i = tid; i < 576; i += THREADS) {
        sw2[i] = w2[i];
        sw3[i] = w3[i];
    }
    for (int i = tid; i < 9248; i += THREADS) p1p[i] = 0.f;
    for (int i = tid; i < 2592; i += THREADS) p2p[i] = 0.f;
    __syncthreads();

    // ================= Stage 1: conv1(2x2,s2) + floor(relu) + pool2 =========
    // Row-pair form: per pool-row dy only 16 input floats live + m[8] maxes.
    const float* xb = x + (size_t)n * (2 * 128 * 128);
    #pragma unroll
    for (int it = 0; it < 4; it++) {
        int pos = tid + it * THREADS;          // 0..1023
        int py = pos >> 5, px = pos & 31;
        const float* src0 = xb + (4 * py) * 128 + 4 * px;   // ch0
        const float* src1 = src0 + 16384;                   // ch1
        float m[8];
        #pragma unroll
        for (int oc = 0; oc < 8; oc++) m[oc] = 0.f;

        #pragma unroll
        for (int dy = 0; dy < 2; dy++) {
            float4 r0a = *reinterpret_cast<const float4*>(src0 + (2*dy)   * 128);
            float4 r0b = *reinterpret_cast<const float4*>(src0 + (2*dy+1) * 128);
            float4 r1a = *reinterpret_cast<const float4*>(src1 + (2*dy)   * 128);
            float4 r1b = *reinterpret_cast<const float4*>(src1 + (2*dy+1) * 128);
            #pragma unroll
            for (int oc = 0; oc < 8; oc++) {
                const float* w = &sw1[oc * 8];
                float a0, a1;
                a0 = r0a.x * w[0];                 a1 = r0a.z * w[0];
                a0 = fmaf(r0a.y, w[1], a0);        a1 = fmaf(r0a.w, w[1], a1);
                a0 = fmaf(r0b.x, w[2], a0);        a1 = fmaf(r0b.z, w[2], a1);
                a0 = fmaf(r0b.y, w[3], a0);        a1 = fmaf(r0b.w, w[3], a1);
                a0 = fmaf(r1a.x, w[4], a0);        a1 = fmaf(r1a.z, w[4], a1);
                a0 = fmaf(r1a.y, w[5], a0);        a1 = fmaf(r1a.w, w[5], a1);
                a0 = fmaf(r1b.x, w[6], a0);        a1 = fmaf(r1b.z, w[6], a1);
                a0 = fmaf(r1b.y, w[7], a0);        a1 = fmaf(r1b.w, w[7], a1);
                m[oc] = fmaxf(m[oc], fmaxf(floorf(fmaxf(a0, 0.f)),
                                           floorf(fmaxf(a1, 0.f))));
            }
        }
        #pragma unroll
        for (int oc = 0; oc < 8; oc++)
            p1p[oc * 1156 + (py + 1) * 34 + (px + 1)] = m[oc];
    }
    __syncthreads();

    // ================= Stage 2: conv2(3x3,p1) + floor(relu) + pool2 =========
    // Thread = 4 oc x 2 adjacent pooled positions, SPLIT over output rows e:
    // per pass acc[4][2][2] (16) + patch[3][6] (18); running max m[4][2].
    {
        int pp  = tid >> 1;          // 0..127 position pair
        int ocg = tid & 1;           // oc base = ocg*4
        int py  = pp >> 3;           // 0..15
        int pxp = pp & 7;            // pooled px = 2*pxp + p

        float m[4][2];
        #pragma unroll
        for (int o = 0; o < 4; o++) { m[o][0] = 0.f; m[o][1] = 0.f; }

        #pragma unroll
        for (int e = 0; e < 2; e++) {
            float acc[4][2][2];      // [o][p][dx]
            #pragma unroll
            for (int o = 0; o < 4; o++)
                #pragma unroll
                for (int p = 0; p < 2; p++) {
                    acc[o][p][0] = 0.f; acc[o][p][1] = 0.f;
                }

            #pragma unroll
            for (int ic = 0; ic < 8; ic++) {
                const float* base = p1p + ic * 1156 + (2 * py + e) * 34 + 4 * pxp;
                float patch[3][6];
                #pragma unroll
                for (int r = 0; r < 3; r++) {
                    float2 a = *reinterpret_cast<const float2*>(base + r * 34);
                    float2 b = *reinterpret_cast<const float2*>(base + r * 34 + 2);
                    float2 c = *reinterpret_cast<const float2*>(base + r * 34 + 4);
                    patch[r][0] = a.x; patch[r][1] = a.y;
                    patch[r][2] = b.x; patch[r][3] = b.y;
                    patch[r][4] = c.x; patch[r][5] = c.y;
                }
                #pragma unroll
                for (int o = 0; o < 4; o++) {
                    const float* wp = &sw2[((ocg * 4 + o) * 8 + ic) * 9];
                    #pragma unroll
                    for (int p = 0; p < 2; p++) {
                        #pragma unroll
                        for (int d = 0; d < 2; d++) {
                            float a = acc[o][p][d];
                            #pragma unroll
                            for (int ky = 0; ky < 3; ky++)
                                #pragma unroll
                                for (int kx = 0; kx < 3; kx++)
                                    a = fmaf(patch[ky][2*p + d + kx],
                                             wp[ky * 3 + kx], a);
                            acc[o][p][d] = a;
                        }
                    }
                }
            }
            #pragma unroll
            for (int o = 0; o < 4; o++)
                #pragma unroll
                for (int p = 0; p < 2; p++) {
                    float v = fmaxf(floorf(fmaxf(acc[o][p][0], 0.f)),
                                    floorf(fmaxf(acc[o][p][1], 0.f)));
                    m[o][p] = fmaxf(m[o][p], v);
                }
        }
        #pragma unroll
        for (int o = 0; o < 4; o++)
            #pragma unroll
            for (int p = 0; p < 2; p++)
                p2p[(ocg * 4 + o) * 324 + (py + 1) * 18 + (2 * pxp + p + 1)]
                    = m[o][p];
    }
    __syncthreads();

    // ================= Stage 3: conv3(3x3,p2) + floor(relu) + pool2 =========
    // 64 pooled positions; 4 threads/pos, 2 out-channels each.
    {
        int pos = tid >> 2;                // 0..63
        int ocg = tid & 3;
        int py = pos >> 3, px = pos & 7;
        float acc[2][2][2];
        #pragma unroll
        for (int j = 0; j < 2; j++)
            #pragma unroll
            for (int a = 0; a < 2; a++)
                #pragma unroll
                for (int b = 0; b < 2; b++) acc[j][a][b] = 0.f;

        #pragma unroll
        for (int ic = 0; ic < 8; ic++) {
            const float* base = p2p + ic * 324 + (2 * py) * 18 + 2 * px;
            float patch[4][4];
            #pragma unroll
            for (int r = 0; r < 4; r++) {
                float2 a = *reinterpret_cast<const float2*>(base + r * 18);
                float2 b = *reinterpret_cast<const float2*>(base + r * 18 + 2);
                patch[r][0] = a.x; patch[r][1] = a.y;
                patch[r][2] = b.x; patch[r][3] = b.y;
            }
            #pragma unroll
            for (int j = 0; j < 2; j++) {
                int oc = ocg * 2 + j;
                const float* w = &sw3[(oc * 8 + ic) * 9];
                #pragma unroll
                for (int dy = 0; dy < 2; dy++) {
                    #pragma unroll
                    for (int dx = 0; dx < 2; dx++) {
                        float a = acc[j][dy][dx];
                        #pragma unroll
                        for (int ky = 0; ky < 3; ky++)
                            #pragma unroll
                            for (int kx = 0; kx < 3; kx++)
                                a = fmaf(patch[dy+ky][dx+kx], w[ky*3+kx], a);
                        acc[j][dy][dx] = a;
                    }
                }
            }
        }
        #pragma unroll
        for (int j = 0; j < 2; j++) {
            int oc = ocg * 2 + j;
            float m = 0.f;
            #pragma unroll
            for (int dy = 0; dy < 2; dy++)
                #pragma unroll
                for (int dx = 0; dx < 2; dx++)
                    m = fmaxf(m, floorf(fmaxf(acc[j][dy][dx], 0.f)));
            p3[oc * 64 + py * 8 + px] = m;     // flatten order c*64 + y*8 + x
        }
    }
    __syncthreads();

    // ================= Stage 4: fc (512 -> 2) ===============================
    {
        float a0 = 0.f, a1 = 0.f;
        #pragma unroll
        for (int k = 0; k < 2; k++) {
            int j = tid + k * THREADS;         // 0..511
            float v = p3[j];
            a0 = fmaf(v, wfc[j],       a0);
            a1 = fmaf(v, wfc[512 + j], a1);
        }
        #pragma unroll
        for (int off = 16; off > 0; off >>= 1) {
            a0 += __shfl_down_sync(0xffffffffu, a0, off);
            a1 += __shfl_down_sync(0xffffffffu, a1, off);
        }
        if ((tid & 31) == 0) {
            red[tid >> 5]       = a0;
            red[8 + (tid >> 5)] = a1;
        }
        __syncthreads();
        if (tid == 0) {
            float s0 = 0.f, s1 = 0.f;
            #pragma unroll
            for (int i = 0; i < 8; i++) { s0 += red[i]; s1 += red[8 + i]; }
            out[n * 2 + 0] = s0;
            out[n * 2 + 1] = s1;
        }
    }
}

extern "C" void kernel_launch(void* const* d_in, const int* in_sizes, int n_in,
                              void* d_out, int out_size)
{
    const float* x   = (const float*)d_in[0];
    const float* w1  = (const float*)d_in[1];
    const float* w2  = (const float*)d_in[2];
    const float* w3  = (const float*)d_in[3];
    const float* wfc = (const float*)d_in[4];
    int nsamples = in_sizes[0] / (2 * 128 * 128);   // 1024

    size_t smem_bytes = SMEM_FLOATS * sizeof(float);  // ~54.3 KB
    cudaFuncSetAttribute(snn_fused_kernel,
                         cudaFuncAttributeMaxDynamicSharedMemorySize,
                         (int)smem_bytes);
    snn_fused_kernel<<<nsamples, THREADS, smem_bytes>>>(x, w1, w2, w3, wfc,
                                                        (float*)d_out);
}

// round 10
// speedup vs baseline: 1.0956x; 1.0956x over previous
#include <cuda_runtime.h>

// SmartDoorClassifierv1 — fused CNN (LIF collapses: alpha = exp(-200) == 0 in fp32).
// Round 9: spill root-cause = full unroll of stage-1 it-loop (ptxas batches
// 4 iterations of LDGs -> ~96 live regs). Fix: #pragma unroll 1 on stage-1
// it-loop and stage-2/3 ic-loops; halo-only zero fill; (256,3) kept.

#define THREADS 256

// dynamic smem layout (float indices)
//  p1p : 8 x 34 x 34 = 9248   (stage-1 pooled, 1-halo)
//  p2p : 8 x 18 x 18 = 2592   (stage-2 pooled, 1-halo)
//  p3  : 512                  (flatten order)
//  sw1 : 64, sw2: 576, sw3: 576, red: 16
#define OFF_P1   0
#define OFF_P2   9248
#define OFF_P3   11840
#define OFF_W1   12352
#define OFF_W2   (OFF_W1 + 64)
#define OFF_W3   (OFF_W2 + 576)
#define OFF_RED  (OFF_W3 + 576)
#define SMEM_FLOATS (OFF_RED + 16)

__global__ __launch_bounds__(THREADS, 3)
void snn_fused_kernel(const float* __restrict__ x,
                      const float* __restrict__ w1,
                      const float* __restrict__ w2,
                      const float* __restrict__ w3,
                      const float* __restrict__ wfc,
                      float* __restrict__ out)
{
    extern __shared__ float smem[];
    float* p1p = smem + OFF_P1;
    float* p2p = smem + OFF_P2;
    float* p3  = smem + OFF_P3;
    float* sw1 = smem + OFF_W1;
    float* sw2 = smem + OFF_W2;
    float* sw3 = smem + OFF_W3;
    float* red = smem + OFF_RED;

    const int tid = threadIdx.x;
    const int n   = blockIdx.x;

    // ---- init: weights + HALO-ONLY zero fill of padded planes ----
    if (tid < 64) sw1[tid] = w1[tid];
    for (int i = tid; i < 576; i += THREADS) {
        sw2[i] = w2[i];
        sw3[i] = w3[i];
    }
    // p1p halo: top/bottom rows (34 each) and left/right cols (rows 1..32)
    for (int i = tid; i < 8 * 34; i += THREADS) {
        int ic = i / 34, c = i % 34;
        p1p[ic * 1156 + c] = 0.f;
        p1p[ic * 1156 + 33 * 34 + c] = 0.f;
    }
    for (int i = tid; i < 8 * 32; i += THREADS) {
        int ic = i / 32, r = (i % 32) + 1;
        p1p[ic * 1156 + r * 34] = 0.f;
        p1p[ic * 1156 + r * 34 + 33] = 0.f;
    }
    // p2p halo
    for (int i = tid; i < 8 * 18; i += THREADS) {
        int ic = i / 18, c = i % 18;
        p2p[ic * 324 + c] = 0.f;
        p2p[ic * 324 + 17 * 18 + c] = 0.f;
    }
    for (int i = tid; i < 8 * 16; i += THREADS) {
        int ic = i / 16, r = (i % 16) + 1;
        p2p[ic * 324 + r * 18] = 0.f;
        p2p[ic * 324 + r * 18 + 17] = 0.f;
    }
    __syncthreads();

    // ================= Stage 1: conv1(2x2,s2) + floor(relu) + pool2 =========
    // Row-pair form. NOTE: unroll 1 — prevents ptxas batching 4 iterations'
    // LDGs (the register spiller at the (256,3) cap).
    const float* xb = x + (size_t)n * (2 * 128 * 128);
    #pragma unroll 1
    for (int it = 0; it < 4; it++) {
        int pos = tid + it * THREADS;          // 0..1023
        int py = pos >> 5, px = pos & 31;
        const float* src0 = xb + (4 * py) * 128 + 4 * px;   // ch0
        const float* src1 = src0 + 16384;                   // ch1
        float m[8];
        #pragma unroll
        for (int oc = 0; oc < 8; oc++) m[oc] = 0.f;

        #pragma unroll
        for (int dy = 0; dy < 2; dy++) {
            float4 r0a = *reinterpret_cast<const float4*>(src0 + (2*dy)   * 128);
            float4 r0b = *reinterpret_cast<const float4*>(src0 + (2*dy+1) * 128);
            float4 r1a = *reinterpret_cast<const float4*>(src1 + (2*dy)   * 128);
            float4 r1b = *reinterpret_cast<const float4*>(src1 + (2*dy+1) * 128);
            #pragma unroll
            for (int oc = 0; oc < 8; oc++) {
                const float* w = &sw1[oc * 8];
                float a0, a1;
                a0 = r0a.x * w[0];                 a1 = r0a.z * w[0];
                a0 = fmaf(r0a.y, w[1], a0);        a1 = fmaf(r0a.w, w[1], a1);
                a0 = fmaf(r0b.x, w[2], a0);        a1 = fmaf(r0b.z, w[2], a1);
                a0 = fmaf(r0b.y, w[3], a0);        a1 = fmaf(r0b.w, w[3], a1);
                a0 = fmaf(r1a.x, w[4], a0);        a1 = fmaf(r1a.z, w[4], a1);
                a0 = fmaf(r1a.y, w[5], a0);        a1 = fmaf(r1a.w, w[5], a1);
                a0 = fmaf(r1b.x, w[6], a0);        a1 = fmaf(r1b.z, w[6], a1);
                a0 = fmaf(r1b.y, w[7], a0);        a1 = fmaf(r1b.w, w[7], a1);
                m[oc] = fmaxf(m[oc], fmaxf(floorf(fmaxf(a0, 0.f)),
                                           floorf(fmaxf(a1, 0.f))));
            }
        }
        #pragma unroll
        for (int oc = 0; oc < 8; oc++)
            p1p[oc * 1156 + (py + 1) * 34 + (px + 1)] = m[oc];
    }
    __syncthreads();

    // ================= Stage 2: conv2(3x3,p1) + floor(relu) + pool2 =========
    // Thread = 4 oc x 2 adjacent pooled positions; shared 4x6 patch per ic.
    // ic loop NOT unrolled: patch live range bounded to one iteration.
    {
        int pp  = tid >> 1;          // 0..127 position pair
        int ocg = tid & 1;           // oc base = ocg*4
        int py  = pp >> 3;           // 0..15
        int pxp = pp & 7;            // pooled px = 2*pxp + p

        float acc[4][2][2][2];       // [o][p][dy][dx] — 32 regs across ic loop
        #pragma unroll
        for (int o = 0; o < 4; o++)
            #pragma unroll
            for (int p = 0; p < 2; p++)
                #pragma unroll
                for (int e = 0; e < 2; e++) {
                    acc[o][p][e][0] = 0.f; acc[o][p][e][1] = 0.f;
                }

        #pragma unroll 1
        for (int ic = 0; ic < 8; ic++) {
            const float* base = p1p + ic * 1156 + (2 * py) * 34 + 4 * pxp;
            float patch[4][6];
            #pragma unroll
            for (int r = 0; r < 4; r++) {
                float2 a = *reinterpret_cast<const float2*>(base + r * 34);
                float2 b = *reinterpret_cast<const float2*>(base + r * 34 + 2);
                float2 c = *reinterpret_cast<const float2*>(base + r * 34 + 4);
                patch[r][0] = a.x; patch[r][1] = a.y;
                patch[r][2] = b.x; patch[r][3] = b.y;
                patch[r][4] = c.x; patch[r][5] = c.y;
            }
            #pragma unroll
            for (int o = 0; o < 4; o++) {
                const float* wp = &sw2[((ocg * 4 + o) * 8 + ic) * 9];
                #pragma unroll
                for (int p = 0; p < 2; p++) {
                    #pragma unroll
                    for (int e = 0; e < 2; e++) {
                        #pragma unroll
                        for (int d = 0; d < 2; d++) {
                            float a = acc[o][p][e][d];
                            #pragma unroll
                            for (int ky = 0; ky < 3; ky++)
                                #pragma unroll
                                for (int kx = 0; kx < 3; kx++)
                                    a = fmaf(patch[e + ky][2*p + d + kx],
                                             wp[ky * 3 + kx], a);
                            acc[o][p][e][d] = a;
                        }
                    }
                }
            }
        }
        #pragma unroll
        for (int o = 0; o < 4; o++) {
            #pragma unroll
            for (int p = 0; p < 2; p++) {
                float m = 0.f;
                #pragma unroll
                for (int e = 0; e < 2; e++)
                    #pragma unroll
                    for (int d = 0; d < 2; d++)
                        m = fmaxf(m, floorf(fmaxf(acc[o][p][e][d], 0.f)));
                p2p[(ocg * 4 + o) * 324 + (py + 1) * 18 + (2 * pxp + p + 1)] = m;
            }
        }
    }
    __syncthreads();

    // ================= Stage 3: conv3(3x3,p2) + floor(relu) + pool2 =========
    // 64 pooled positions; 4 threads/pos, 2 out-channels each. ic not unrolled.
    {
        int pos = tid >> 2;                // 0..63
        int ocg = tid & 3;
        int py = pos >> 3, px = pos & 7;
        float acc[2][2][2];
        #pragma unroll
        for (int j = 0; j < 2; j++)
            #pragma unroll
            for (int a = 0; a < 2; a++)
                #pragma unroll
                for (int b = 0; b < 2; b++) acc[j][a][b] = 0.f;

        #pragma unroll 1
        for (int ic = 0; ic < 8; ic++) {
            const float* base = p2p + ic * 324 + (2 * py) * 18 + 2 * px;
            float patch[4][4];
            #pragma unroll
            for (int r = 0; r < 4; r++) {
                float2 a = *reinterpret_cast<const float2*>(base + r * 18);
                float2 b = *reinterpret_cast<const float2*>(base + r * 18 + 2);
                patch[r][0] = a.x; patch[r][1] = a.y;
                patch[r][2] = b.x; patch[r][3] = b.y;
            }
            #pragma unroll
            for (int j = 0; j < 2; j++) {
                const float* w = &sw3[((ocg * 2 + j) * 8 + ic) * 9];
                #pragma unroll
                for (int dy = 0; dy < 2; dy++) {
                    #pragma unroll
                    for (int dx = 0; dx < 2; dx++) {
                        float a = acc[j][dy][dx];
                        #pragma unroll
                        for (int ky = 0; ky < 3; ky++)
                            #pragma unroll
                            for (int kx = 0; kx < 3; kx++)
                                a = fmaf(patch[dy+ky][dx+kx], w[ky*3+kx], a);
                        acc[j][dy][dx] = a;
                    }
                }
            }
        }
        #pragma unroll
        for (int j = 0; j < 2; j++) {
            int oc = ocg * 2 + j;
            float m = 0.f;
            #pragma unroll
            for (int dy = 0; dy < 2; dy++)
                #pragma unroll
                for (int dx = 0; dx < 2; dx++)
                    m = fmaxf(m, floorf(fmaxf(acc[j][dy][dx], 0.f)));
            p3[oc * 64 + py * 8 + px] = m;     // flatten order c*64 + y*8 + x
        }
    }
    __syncthreads();

    // ================= Stage 4: fc (512 -> 2) ===============================
    {
        float a0 = 0.f, a1 = 0.f;
        #pragma unroll
        for (int k = 0; k < 2; k++) {
            int j = tid + k * THREADS;         // 0..511
            float v = p3[j];
            a0 = fmaf(v, wfc[j],       a0);
            a1 = fmaf(v, wfc[512 + j], a1);
        }
        #pragma unroll
        for (int off = 16; off > 0; off >>= 1) {
            a0 += __shfl_down_sync(0xffffffffu, a0, off);
            a1 += __shfl_down_sync(0xffffffffu, a1, off);
        }
        if ((tid & 31) == 0) {
            red[tid >> 5]       = a0;
            red[8 + (tid >> 5)] = a1;
        }
        __syncthreads();
        if (tid == 0) {
            float s0 = 0.f, s1 = 0.f;
            #pragma unroll
            for (int i = 0; i < 8; i++) { s0 += red[i]; s1 += red[8 + i]; }
            out[n * 2 + 0] = s0;
            out[n * 2 + 1] = s1;
        }
    }
}

extern "C" void kernel_launch(void* const* d_in, const int* in_sizes, int n_in,
                              void* d_out, int out_size)
{
    const float* x   = (const float*)d_in[0];
    const float* w1  = (const float*)d_in[1];
    const float* w2  = (const float*)d_in[2];
    const float* w3  = (const float*)d_in[3];
    const float* wfc = (const float*)d_in[4];
    int nsamples = in_sizes[0] / (2 * 128 * 128);   // 1024

    size_t smem_bytes = SMEM_FLOATS * sizeof(float);  // ~54.3 KB
    cudaFuncSetAttribute(snn_fused_kernel,
                         cudaFuncAttributeMaxDynamicSharedMemorySize,
                         (int)smem_bytes);
    snn_fused_kernel<<<nsamples, THREADS, smem_bytes>>>(x, w1, w2, w3, wfc,
                                                        (float*)d_out);
}